// round 1
// baseline (speedup 1.0000x reference)
#include <cuda_runtime.h>
#include <cstdint>
#include <cstddef>

#define N_NODES 10000
#define E_ 320
#define D_ 15
#define T_ 16          // tokens per side = D+1
#define OUT_ 30
#define SROW 321       // padded smem row stride (bank-conflict-free)
#define UK 656         // padded K for the U @ MVcat GEMM (640 data + 2 rank-1 + 14 pad)

// ---------------- scratch (device globals; no runtime allocation) ----------------
__device__ float g_MA[6 * E_ * E_];              // composed QKV matrices [1920][320], M[j][i]
__device__ float g_Mq[E_ * E_];                  // fin q  from ctx_in  (fin_wq @ in_o_w)
__device__ float g_MKin[E_ * E_];                // fin k  from ctx_in
__device__ float g_MKout[E_ * E_];               // fin k  from ctx_out
__device__ float g_MVcat[E_ * UK];               // [320][656]: [MVin | MVout | cv_in | cv_out | 0-pad]
__device__ float g_PW[E_ * OUT_];                // fin_o_w^T @ W
__device__ float g_cq[E_];
__device__ float g_ckin[E_];
__device__ float g_ckout[E_];
__device__ float g_cW[32];
__device__ float g_XP[(size_t)N_NODES * 1920];   // X @ MA^T  (all 6 QKV projections)
__device__ float g_CTX[(size_t)N_NODES * 2 * T_ * E_];  // per-node attention contexts (pre out-proj)
__device__ float g_Qf[(size_t)N_NODES * E_];     // final query
__device__ float g_Tin[(size_t)N_NODES * E_];    // Pk_in^T q
__device__ float g_Tout[(size_t)N_NODES * E_];
__device__ float g_U[(size_t)N_NODES * UK];      // [Uin | Uout | sa_in | sa_out | 0]
__device__ float g_O[(size_t)N_NODES * E_];      // final attention output (pre out-proj)

// ---------------- generic tiled fp32 GEMM ----------------
// NT: C[m][n] = sum_k A[m][k] * B[n][k]   (B row-major [N][K])
// NN: C[m][n] = sum_k A[m][k] * B[k][n]   (B row-major [K][N])
// requires K % 16 == 0
template <bool NT>
__global__ void __launch_bounds__(256) gemm_kernel(
    const float* __restrict__ A, int lda,
    const float* __restrict__ B, int ldb,
    float* __restrict__ C, int ldc,
    int M, int N, int K,
    const float* __restrict__ bias)
{
    __shared__ float As[64][17];
    __shared__ float Bs[64][17];
    int tid = threadIdx.x;
    int tx = tid & 15, ty = tid >> 4;
    int m0 = blockIdx.y * 64, n0 = blockIdx.x * 64;
    float acc[4][4] = {};

    for (int k0 = 0; k0 < K; k0 += 16) {
        #pragma unroll
        for (int i = 0; i < 4; i++) {
            int li = tid + 256 * i;
            int k = li & 15, m = li >> 4;
            int gm = m0 + m;
            As[m][k] = (gm < M) ? A[(size_t)gm * lda + k0 + k] : 0.f;
        }
        if (NT) {
            #pragma unroll
            for (int i = 0; i < 4; i++) {
                int li = tid + 256 * i;
                int k = li & 15, nn = li >> 4;
                int gn = n0 + nn;
                Bs[nn][k] = (gn < N) ? B[(size_t)gn * ldb + k0 + k] : 0.f;
            }
        } else {
            #pragma unroll
            for (int i = 0; i < 4; i++) {
                int li = tid + 256 * i;
                int nn = li & 63, k = li >> 6;
                int gn = n0 + nn;
                Bs[nn][k] = (gn < N) ? B[(size_t)(k0 + k) * ldb + gn] : 0.f;
            }
        }
        __syncthreads();
        #pragma unroll
        for (int kk = 0; kk < 16; kk++) {
            float af[4], bf[4];
            #pragma unroll
            for (int r = 0; r < 4; r++) af[r] = As[ty * 4 + r][kk];
            #pragma unroll
            for (int c = 0; c < 4; c++) bf[c] = Bs[tx * 4 + c][kk];
            #pragma unroll
            for (int r = 0; r < 4; r++)
                #pragma unroll
                for (int c = 0; c < 4; c++)
                    acc[r][c] += af[r] * bf[c];
        }
        __syncthreads();
    }
    #pragma unroll
    for (int r = 0; r < 4; r++) {
        int gm = m0 + ty * 4 + r;
        if (gm >= M) continue;
        #pragma unroll
        for (int c = 0; c < 4; c++) {
            int gn = n0 + tx * 4 + c;
            if (gn < N)
                C[(size_t)gm * ldc + gn] = acc[r][c] + (bias ? bias[gn] : 0.f);
        }
    }
}

// ---------------- small composed constants ----------------
__global__ void __launch_bounds__(256) compose_small(
    const float* __restrict__ finw, const float* __restrict__ finb,
    const float* __restrict__ fow,  const float* __restrict__ fob,
    const float* __restrict__ inob, const float* __restrict__ outob,
    const float* __restrict__ W)
{
    int id = blockIdx.x * 256 + threadIdx.x;
    if (id < 9600) {                       // PW[c][o] = sum_k fo_w[k][c] * W[k][o]
        int c = id / OUT_, o = id % OUT_;
        float acc = 0.f;
        for (int k = 0; k < E_; k++) acc += fow[k * E_ + c] * W[k * OUT_ + o];
        g_PW[c * OUT_ + o] = acc;
    } else if (id < 9632) {                // cW[o] = sum_k fo_b[k] * W[k][o]
        int o = id - 9600;
        if (o < OUT_) {
            float acc = 0.f;
            for (int k = 0; k < E_; k++) acc += fob[k] * W[k * OUT_ + o];
            g_cW[o] = acc;
        }
    } else if (id < 9952) {                // cq[j]
        int j = id - 9632;
        float acc = finb[j];
        for (int k = 0; k < E_; k++) acc += finw[j * E_ + k] * inob[k];
        g_cq[j] = acc;
    } else if (id < 10272) {               // ckin[j]
        int j = id - 9952;
        float acc = finb[E_ + j];
        for (int k = 0; k < E_; k++) acc += finw[(E_ + j) * E_ + k] * inob[k];
        g_ckin[j] = acc;
    } else if (id < 10592) {               // ckout[j]
        int j = id - 10272;
        float acc = finb[E_ + j];
        for (int k = 0; k < E_; k++) acc += finw[(E_ + j) * E_ + k] * outob[k];
        g_ckout[j] = acc;
    } else if (id < 10912) {               // cv_in -> MVcat col 640
        int j = id - 10592;
        float acc = finb[2 * E_ + j];
        for (int k = 0; k < E_; k++) acc += finw[(2 * E_ + j) * E_ + k] * inob[k];
        g_MVcat[j * UK + 640] = acc;
    } else if (id < 11232) {               // cv_out -> MVcat col 641
        int j = id - 10912;
        float acc = finb[2 * E_ + j];
        for (int k = 0; k < E_; k++) acc += finw[(2 * E_ + j) * E_ + k] * outob[k];
        g_MVcat[j * UK + 641] = acc;
    } else if (id < 11232 + 320 * 14) {    // zero pad cols 642..655
        int r = id - 11232;
        int j = r / 14, cc = 642 + r % 14;
        g_MVcat[j * UK + cc] = 0.f;
    }
}

// ---------------- per-node 5-head attention (in & out sides) ----------------
// reads Q/K/V rows from g_XP (gather), writes ctx (pre out-proj) to g_CTX
__global__ void __launch_bounds__(256) attn_kernel(
    const int* __restrict__ in_idx, const int* __restrict__ out_idx,
    const float* __restrict__ in_qkv_b, const float* __restrict__ out_qkv_b)
{
    int n = blockIdx.x;
    int tid = threadIdx.x;
    extern __shared__ float sm[];
    float* Qs = sm;                       // 16*SROW
    float* Ks = Qs + T_ * SROW;
    float* Vs = Ks + T_ * SROW;
    float* As = Vs + T_ * SROW;           // 5*16*16 softmax probs
    __shared__ int rows[T_];

    for (int side = 0; side < 2; side++) {
        const int* idx = side ? out_idx : in_idx;
        const float* bias = side ? out_qkv_b : in_qkv_b;
        if (tid < T_) rows[tid] = (tid == 0) ? n : idx[n * D_ + tid - 1];
        __syncthreads();
        int colbase = side * 960;
        // gather Q,K,V rows (+ qkv bias)
        for (int e = tid; e < T_ * E_; e += 256) {
            int t = e / E_, j = e - t * E_;
            const float* xp = g_XP + (size_t)rows[t] * 1920 + colbase;
            Qs[t * SROW + j] = xp[j] + bias[j];
            Ks[t * SROW + j] = xp[E_ + j] + bias[E_ + j];
            Vs[t * SROW + j] = xp[2 * E_ + j] + bias[2 * E_ + j];
        }
        __syncthreads();
        // scores: 5 heads x 16 x 16, hd=64, scale 1/8
        for (int e = tid; e < 5 * 256; e += 256) {
            int m = e & 15, l = (e >> 4) & 15, h = e >> 8;
            const float* q = &Qs[l * SROW + h * 64];
            const float* k = &Ks[m * SROW + h * 64];
            float acc = 0.f;
            #pragma unroll
            for (int d = 0; d < 64; d++) acc += q[d] * k[d];
            As[e] = acc * 0.125f;
        }
        __syncthreads();
        // softmax per (h,l): 80 rows of 16
        if (tid < 80) {
            float* row = &As[tid * 16];
            float mx = row[0];
            #pragma unroll
            for (int m2 = 1; m2 < 16; m2++) mx = fmaxf(mx, row[m2]);
            float ex[16], ssum = 0.f;
            #pragma unroll
            for (int m2 = 0; m2 < 16; m2++) { ex[m2] = __expf(row[m2] - mx); ssum += ex[m2]; }
            float inv = 1.f / ssum;
            #pragma unroll
            for (int m2 = 0; m2 < 16; m2++) row[m2] = ex[m2] * inv;
        }
        __syncthreads();
        // ctx = A @ V  -> global
        float* ctxout = g_CTX + (size_t)n * (2 * T_ * E_) + (size_t)side * (T_ * E_);
        for (int e = tid; e < T_ * E_; e += 256) {
            int t = e / E_, j = e - t * E_;
            int h = j >> 6;
            const float* a = &As[(h * 16 + t) * 16];
            float acc = 0.f;
            #pragma unroll
            for (int m2 = 0; m2 < 16; m2++) acc += a[m2] * Vs[m2 * SROW + j];
            ctxout[e] = acc;
        }
        __syncthreads();
    }
}

// ---------------- final-layer scores + softmax + weighted sums ----------------
__global__ void __launch_bounds__(256) finscore_kernel()
{
    int n = blockIdx.x;
    int tid = threadIdx.x, lane = tid & 31, w = tid >> 5;
    __shared__ float Ts[2 * E_];
    __shared__ float sA[32];
    __shared__ float sc[2];
    __shared__ float s_sain;
    const float* ctxn = g_CTX + (size_t)n * (2 * T_ * E_);

    for (int i = tid; i < E_; i += 256) {
        Ts[i]      = g_Tin[(size_t)n * E_ + i];
        Ts[E_ + i] = g_Tout[(size_t)n * E_ + i];
    }
    __syncthreads();
    // 32 token score dots: warp w -> tokens w*4 .. w*4+3
    #pragma unroll
    for (int ii = 0; ii < 4; ii++) {
        int t = w * 4 + ii;
        int side = t >> 4, tok = t & 15;
        const float* cr = ctxn + side * (T_ * E_) + tok * E_;
        const float* tv = Ts + side * E_;
        float acc = 0.f;
        #pragma unroll
        for (int i = 0; i < 10; i++) acc += cr[lane + 32 * i] * tv[lane + 32 * i];
        #pragma unroll
        for (int o = 16; o; o >>= 1) acc += __shfl_xor_sync(0xffffffffu, acc, o);
        if (lane == 0) sA[t] = acc;
    }
    if (w < 2) {  // q . ck constants
        const float* q = g_Qf + (size_t)n * E_;
        const float* ck = w ? g_ckout : g_ckin;
        float acc = 0.f;
        #pragma unroll
        for (int i = 0; i < 10; i++) acc += q[lane + 32 * i] * ck[lane + 32 * i];
        #pragma unroll
        for (int o = 16; o; o >>= 1) acc += __shfl_xor_sync(0xffffffffu, acc, o);
        if (lane == 0) sc[w] = acc;
    }
    __syncthreads();
    if (tid < 32) {  // softmax over 32 (hd=320 -> scale 320^-0.5)
        float v = (sA[tid] + sc[tid >> 4]) * 0.05590169943749474f;
        float mx = v;
        #pragma unroll
        for (int o = 16; o; o >>= 1) mx = fmaxf(mx, __shfl_xor_sync(0xffffffffu, mx, o));
        float e = __expf(v - mx);
        float ssum = e;
        #pragma unroll
        for (int o = 16; o; o >>= 1) ssum += __shfl_xor_sync(0xffffffffu, ssum, o);
        float a = e / ssum;
        sA[tid] = a;
        float ain = (tid < 16) ? a : 0.f;
        #pragma unroll
        for (int o = 16; o; o >>= 1) ain += __shfl_xor_sync(0xffffffffu, ain, o);
        if (tid == 0) s_sain = ain;
    }
    __syncthreads();
    float sain = s_sain;
    float* urow = g_U + (size_t)n * UK;
    for (int i = tid; i < UK; i += 256) {
        if (i < E_) {
            float acc = 0.f;
            #pragma unroll
            for (int t = 0; t < 16; t++) acc += sA[t] * ctxn[t * E_ + i];
            urow[i] = acc;
        } else if (i < 2 * E_) {
            int ii2 = i - E_;
            float acc = 0.f;
            #pragma unroll
            for (int t = 0; t < 16; t++) acc += sA[16 + t] * ctxn[T_ * E_ + t * E_ + ii2];
            urow[i] = acc;
        } else if (i == 640) urow[i] = sain;
        else if (i == 641) urow[i] = 1.f - sain;
        else urow[i] = 0.f;
    }
}

// ---------------- final projection (composed fin_o_w^T @ W) + ELU ----------------
__global__ void __launch_bounds__(256) final_kernel(float* __restrict__ out)
{
    int n0 = blockIdx.x * 8;
    __shared__ float Os[8 * E_];
    int tid = threadIdx.x;
    for (int e = tid; e < 8 * E_; e += 256) {
        int nn = e / E_, j = e - nn * E_;
        int n = n0 + nn;
        Os[e] = (n < N_NODES) ? g_O[(size_t)n * E_ + j] : 0.f;
    }
    __syncthreads();
    int nn = tid >> 5, o = tid & 31;
    int n = n0 + nn;
    if (o < OUT_ && n < N_NODES) {
        const float* orow = Os + nn * E_;
        float a0 = 0.f, a1 = 0.f, a2 = 0.f, a3 = 0.f;
        for (int c = 0; c < E_; c += 4) {
            a0 += orow[c]     * g_PW[c * OUT_ + o];
            a1 += orow[c + 1] * g_PW[(c + 1) * OUT_ + o];
            a2 += orow[c + 2] * g_PW[(c + 2) * OUT_ + o];
            a3 += orow[c + 3] * g_PW[(c + 3) * OUT_ + o];
        }
        float acc = ((a0 + a1) + (a2 + a3)) + g_cW[o];
        out[n * OUT_ + o] = acc > 0.f ? acc : expm1f(acc);
    }
}

// ---------------- host ----------------
extern "C" void kernel_launch(void* const* d_in, const int* in_sizes, int n_in,
                              void* d_out, int out_size)
{
    const float* X         = (const float*)d_in[0];
    const int*   in_idx    = (const int*)  d_in[1];
    const int*   out_idx   = (const int*)  d_in[2];
    const float* in_Wq     = (const float*)d_in[3];
    const float* in_Wk     = (const float*)d_in[4];
    const float* in_Wv     = (const float*)d_in[5];
    const float* in_qkv_w  = (const float*)d_in[6];
    const float* in_qkv_b  = (const float*)d_in[7];
    const float* in_o_w    = (const float*)d_in[8];
    const float* in_o_b    = (const float*)d_in[9];
    const float* out_Wq    = (const float*)d_in[10];
    const float* out_Wk    = (const float*)d_in[11];
    const float* out_Wv    = (const float*)d_in[12];
    const float* out_qkv_w = (const float*)d_in[13];
    const float* out_qkv_b = (const float*)d_in[14];
    const float* out_o_w   = (const float*)d_in[15];
    const float* out_o_b   = (const float*)d_in[16];
    const float* fin_qkv_w = (const float*)d_in[17];
    const float* fin_qkv_b = (const float*)d_in[18];
    const float* fin_o_w   = (const float*)d_in[19];
    const float* fin_o_b   = (const float*)d_in[20];
    const float* Wmat      = (const float*)d_in[21];
    float* out = (float*)d_out;

    float *pMA, *pMq, *pMKin, *pMKout, *pMVcat, *pXP, *pCTX, *pQf, *pTin, *pTout, *pU, *pO, *pcq;
    cudaGetSymbolAddress((void**)&pMA, g_MA);
    cudaGetSymbolAddress((void**)&pMq, g_Mq);
    cudaGetSymbolAddress((void**)&pMKin, g_MKin);
    cudaGetSymbolAddress((void**)&pMKout, g_MKout);
    cudaGetSymbolAddress((void**)&pMVcat, g_MVcat);
    cudaGetSymbolAddress((void**)&pXP, g_XP);
    cudaGetSymbolAddress((void**)&pCTX, g_CTX);
    cudaGetSymbolAddress((void**)&pQf, g_Qf);
    cudaGetSymbolAddress((void**)&pTin, g_Tin);
    cudaGetSymbolAddress((void**)&pTout, g_Tout);
    cudaGetSymbolAddress((void**)&pU, g_U);
    cudaGetSymbolAddress((void**)&pO, g_O);
    cudaGetSymbolAddress((void**)&pcq, g_cq);

    const int ATTN_SMEM = (3 * T_ * SROW + 5 * 16 * 16) * (int)sizeof(float);
    cudaFuncSetAttribute(attn_kernel, cudaFuncAttributeMaxDynamicSharedMemorySize, ATTN_SMEM);

    dim3 gS(5, 5);                  // 320x320 composes
    dim3 gXP(1920 / 64, (N_NODES + 63) / 64);
    dim3 g320(E_ / 64, (N_NODES + 63) / 64);

    // 1) compose QKV matrices: MA[s][j][i] = sum_k qkv_w_s[j][k] * W_s[i][k]
    const float* Ws[6] = {in_Wq, in_Wk, in_Wv, out_Wq, out_Wk, out_Wv};
    const float* Qw[6] = {in_qkv_w, in_qkv_w + E_ * E_, in_qkv_w + 2 * E_ * E_,
                          out_qkv_w, out_qkv_w + E_ * E_, out_qkv_w + 2 * E_ * E_};
    for (int s = 0; s < 6; s++)
        gemm_kernel<true><<<gS, 256>>>(Qw[s], E_, Ws[s], E_, pMA + s * E_ * E_, E_,
                                       E_, E_, E_, nullptr);
    // 2) compose final-layer matrices (fin_w* @ o_w, NN)
    gemm_kernel<false><<<gS, 256>>>(fin_qkv_w,             E_, in_o_w,  E_, pMq,         E_, E_, E_, E_, nullptr);
    gemm_kernel<false><<<gS, 256>>>(fin_qkv_w + E_ * E_,   E_, in_o_w,  E_, pMKin,       E_, E_, E_, E_, nullptr);
    gemm_kernel<false><<<gS, 256>>>(fin_qkv_w + E_ * E_,   E_, out_o_w, E_, pMKout,      E_, E_, E_, E_, nullptr);
    gemm_kernel<false><<<gS, 256>>>(fin_qkv_w + 2 * E_ * E_, E_, in_o_w,  E_, pMVcat,       UK, E_, E_, E_, nullptr);
    gemm_kernel<false><<<gS, 256>>>(fin_qkv_w + 2 * E_ * E_, E_, out_o_w, E_, pMVcat + E_,  UK, E_, E_, E_, nullptr);
    // 3) small composed constants
    compose_small<<<62, 256>>>(fin_qkv_w, fin_qkv_b, fin_o_w, fin_o_b, in_o_b, out_o_b, Wmat);
    // 4) XP = X @ MA^T  : all QKV projections of every node, once
    gemm_kernel<true><<<gXP, 256>>>(X, E_, pMA, E_, pXP, 1920, N_NODES, 1920, E_, nullptr);
    // 5) per-node in/out attention (gather from XP)
    attn_kernel<<<N_NODES, 256, ATTN_SMEM>>>(in_idx, out_idx, in_qkv_b, out_qkv_b);
    // 6) Qf = ctx_in[:,0,:] @ Mq^T + cq
    gemm_kernel<true><<<g320, 256>>>(pCTX, 2 * T_ * E_, pMq, E_, pQf, E_,
                                     N_NODES, E_, E_, pcq);
    // 7) Tin = Qf @ MKin ; Tout = Qf @ MKout   (NN)
    gemm_kernel<false><<<g320, 256>>>(pQf, E_, pMKin,  E_, pTin,  E_, N_NODES, E_, E_, nullptr);
    gemm_kernel<false><<<g320, 256>>>(pQf, E_, pMKout, E_, pTout, E_, N_NODES, E_, E_, nullptr);
    // 8) final scores + softmax + weighted ctx sums -> U
    finscore_kernel<<<N_NODES, 256>>>();
    // 9) O = U @ MVcat^T   (includes rank-1 bias terms via cols 640/641)
    gemm_kernel<true><<<g320, 256>>>(pU, UK, pMVcat, UK, pO, E_, N_NODES, E_, UK, nullptr);
    // 10) out = elu(O @ PW + cW)
    final_kernel<<<(N_NODES + 7) / 8, 256>>>(out);
}

// round 5
// speedup vs baseline: 1.5795x; 1.5795x over previous
#include <cuda_runtime.h>
#include <cstdint>
#include <cstddef>

#define N_NODES 10000
#define E_ 320
#define D_ 15
#define T_ 16
#define OUT_ 30
#define UK 656
#define SR 324

// ---------------- scratch (device globals) ----------------
__device__ float g_MA[6 * E_ * E_];        // composed QKV mats [1920][320]
__device__ float g_Mq[E_ * E_];
__device__ float g_MKin[E_ * E_];
__device__ float g_MKout[E_ * E_];
__device__ float g_MVin[E_ * E_];
__device__ float g_MVout[E_ * E_];
__device__ float g_PW[E_ * 32];            // fo_w^T @ W, padded to 32 cols
__device__ float g_MqKcat[E_ * 640];       // [320][640] = [Mq^T MKin | Mq^T MKout]
__device__ float g_G[UK * 32];             // [656][32] out-projection matrix
__device__ float g_cq[E_];
__device__ float g_ckin[E_];
__device__ float g_ckout[E_];
__device__ float g_cvin[E_];
__device__ float g_cvout[E_];
__device__ float g_cW[32];
__device__ float g_wv[640];                // [win | wout]
__device__ float g_wb[2];                  // bin, bout
__device__ float g_cqK[640];               // [cq@MKin | cq@MKout]
__device__ float g_XP[(size_t)N_NODES * 1920];
__device__ float g_CTX[(size_t)N_NODES * 10240];
__device__ float g_TT[(size_t)N_NODES * 640];
__device__ float g_U[(size_t)(N_NODES + 32) * UK];

struct GemmDesc {
    const float* A; const float* B; float* C; const float* bias;
    int M, N, K, lda, ldb, ldc, op;  // op: 0=NT, 1=NN, 2=TN
};
struct GemmBatch { GemmDesc d[12]; };

// ---------------- big GEMM: 128x128 tile, 8x8 micro, float4 ----------------
__global__ void __launch_bounds__(256) sgemm128(GemmDesc g)
{
    __shared__ float As[16][132];
    __shared__ float Bs[16][132];
    int tid = threadIdx.x;
    int tx = tid & 15, ty = tid >> 4;
    int m0 = blockIdx.y * 128, n0 = blockIdx.x * 128;
    if (m0 >= g.M || n0 >= g.N) return;
    float acc[8][8] = {};

    for (int k0 = 0; k0 < g.K; k0 += 16) {
        // A tile (A is [M][K] for op 0/1)
        #pragma unroll
        for (int i = 0; i < 2; i++) {
            int s = tid + 256 * i;
            int m = s >> 2, kq = (s & 3) << 2;
            int gm = m0 + m;
            float4 v = make_float4(0.f, 0.f, 0.f, 0.f);
            if (gm < g.M) v = *(const float4*)(g.A + (size_t)gm * g.lda + k0 + kq);
            As[kq + 0][m] = v.x; As[kq + 1][m] = v.y;
            As[kq + 2][m] = v.z; As[kq + 3][m] = v.w;
        }
        // B tile
        if (g.op == 0) {      // NT: B [N][K]
            #pragma unroll
            for (int i = 0; i < 2; i++) {
                int s = tid + 256 * i;
                int n = s >> 2, kq = (s & 3) << 2;
                int gn = n0 + n;
                float4 v = make_float4(0.f, 0.f, 0.f, 0.f);
                if (gn < g.N) v = *(const float4*)(g.B + (size_t)gn * g.ldb + k0 + kq);
                Bs[kq + 0][n] = v.x; Bs[kq + 1][n] = v.y;
                Bs[kq + 2][n] = v.z; Bs[kq + 3][n] = v.w;
            }
        } else {              // NN: B [K][N]
            #pragma unroll
            for (int i = 0; i < 2; i++) {
                int s = tid + 256 * i;
                int k = s >> 5, nq = (s & 31) << 2;
                int gn = n0 + nq;
                float4 v = make_float4(0.f, 0.f, 0.f, 0.f);
                if (((g.ldb & 3) == 0) && (gn + 3 < g.N)) {
                    v = *(const float4*)(g.B + (size_t)(k0 + k) * g.ldb + gn);
                } else {
                    const float* bp = g.B + (size_t)(k0 + k) * g.ldb;
                    if (gn + 0 < g.N) v.x = bp[gn + 0];
                    if (gn + 1 < g.N) v.y = bp[gn + 1];
                    if (gn + 2 < g.N) v.z = bp[gn + 2];
                    if (gn + 3 < g.N) v.w = bp[gn + 3];
                }
                *(float4*)&Bs[k][nq] = v;
            }
        }
        __syncthreads();
        #pragma unroll
        for (int kk = 0; kk < 16; kk++) {
            float a[8], b[8];
            *(float4*)&a[0] = *(float4*)&As[kk][ty * 8];
            *(float4*)&a[4] = *(float4*)&As[kk][ty * 8 + 4];
            *(float4*)&b[0] = *(float4*)&Bs[kk][tx * 8];
            *(float4*)&b[4] = *(float4*)&Bs[kk][tx * 8 + 4];
            #pragma unroll
            for (int r = 0; r < 8; r++)
                #pragma unroll
                for (int c = 0; c < 8; c++)
                    acc[r][c] += a[r] * b[c];
        }
        __syncthreads();
    }
    #pragma unroll
    for (int r = 0; r < 8; r++) {
        int gm = m0 + ty * 8 + r;
        if (gm >= g.M) break;
        #pragma unroll
        for (int c = 0; c < 8; c++) {
            int gn = n0 + tx * 8 + c;
            if (gn < g.N)
                g.C[(size_t)gm * g.ldc + gn] = acc[r][c] + (g.bias ? g.bias[gn] : 0.f);
        }
    }
}

// ---------------- small batched GEMM: 64x64 tile, 4x4 micro ----------------
__global__ void __launch_bounds__(256) sgemm64(GemmBatch batch)
{
    GemmDesc g = batch.d[blockIdx.z];
    int m0 = blockIdx.y * 64, n0 = blockIdx.x * 64;
    if (m0 >= g.M || n0 >= g.N) return;
    __shared__ float As[64][17];
    __shared__ float Bs[64][17];
    int tid = threadIdx.x;
    int tx = tid & 15, ty = tid >> 4;
    float acc[4][4] = {};

    for (int k0 = 0; k0 < g.K; k0 += 16) {
        if (g.op == 2) {   // A [K][M]
            #pragma unroll
            for (int i = 0; i < 4; i++) {
                int li = tid + 256 * i;
                int m = li & 63, k = li >> 6;
                int gm = m0 + m;
                As[m][k] = (gm < g.M) ? g.A[(size_t)(k0 + k) * g.lda + gm] : 0.f;
            }
        } else {           // A [M][K]
            #pragma unroll
            for (int i = 0; i < 4; i++) {
                int li = tid + 256 * i;
                int k = li & 15, m = li >> 4;
                int gm = m0 + m;
                As[m][k] = (gm < g.M) ? g.A[(size_t)gm * g.lda + k0 + k] : 0.f;
            }
        }
        if (g.op == 0) {   // B [N][K]
            #pragma unroll
            for (int i = 0; i < 4; i++) {
                int li = tid + 256 * i;
                int k = li & 15, n = li >> 4;
                int gn = n0 + n;
                Bs[n][k] = (gn < g.N) ? g.B[(size_t)gn * g.ldb + k0 + k] : 0.f;
            }
        } else {           // B [K][N]
            #pragma unroll
            for (int i = 0; i < 4; i++) {
                int li = tid + 256 * i;
                int n = li & 63, k = li >> 6;
                int gn = n0 + n;
                Bs[n][k] = (gn < g.N) ? g.B[(size_t)(k0 + k) * g.ldb + gn] : 0.f;
            }
        }
        __syncthreads();
        #pragma unroll
        for (int kk = 0; kk < 16; kk++) {
            float af[4], bf[4];
            #pragma unroll
            for (int r = 0; r < 4; r++) af[r] = As[ty * 4 + r][kk];
            #pragma unroll
            for (int c = 0; c < 4; c++) bf[c] = Bs[tx * 4 + c][kk];
            #pragma unroll
            for (int r = 0; r < 4; r++)
                #pragma unroll
                for (int c = 0; c < 4; c++)
                    acc[r][c] += af[r] * bf[c];
        }
        __syncthreads();
    }
    #pragma unroll
    for (int r = 0; r < 4; r++) {
        int gm = m0 + ty * 4 + r;
        if (gm >= g.M) continue;
        #pragma unroll
        for (int c = 0; c < 4; c++) {
            int gn = n0 + tx * 4 + c;
            if (gn < g.N)
                g.C[(size_t)gm * g.ldc + gn] = acc[r][c] + (g.bias ? g.bias[gn] : 0.f);
        }
    }
}

// ---------------- small raw-input vectors + zero init of G ----------------
__global__ void __launch_bounds__(256) compose_small2(
    const float* __restrict__ finw, const float* __restrict__ finb,
    const float* __restrict__ fob,
    const float* __restrict__ inob, const float* __restrict__ outob,
    const float* __restrict__ W)
{
    int id = blockIdx.x * 256 + threadIdx.x;
    if (id < 320) {                       // cq
        int j = id;
        float acc = finb[j];
        for (int k = 0; k < E_; k++) acc += finw[j * E_ + k] * inob[k];
        g_cq[j] = acc;
    } else if (id < 640) {                // ckin
        int j = id - 320;
        float acc = finb[E_ + j];
        for (int k = 0; k < E_; k++) acc += finw[(E_ + j) * E_ + k] * inob[k];
        g_ckin[j] = acc;
    } else if (id < 960) {                // ckout
        int j = id - 640;
        float acc = finb[E_ + j];
        for (int k = 0; k < E_; k++) acc += finw[(E_ + j) * E_ + k] * outob[k];
        g_ckout[j] = acc;
    } else if (id < 1280) {               // cvin
        int j = id - 960;
        float acc = finb[2 * E_ + j];
        for (int k = 0; k < E_; k++) acc += finw[(2 * E_ + j) * E_ + k] * inob[k];
        g_cvin[j] = acc;
    } else if (id < 1600) {               // cvout
        int j = id - 1280;
        float acc = finb[2 * E_ + j];
        for (int k = 0; k < E_; k++) acc += finw[(2 * E_ + j) * E_ + k] * outob[k];
        g_cvout[j] = acc;
    } else if (id < 1632) {               // cW (30, pad 32)
        int o = id - 1600;
        float acc = 0.f;
        if (o < OUT_)
            for (int k = 0; k < E_; k++) acc += fob[k] * W[k * OUT_ + o];
        g_cW[o] = acc;
    } else if (id < 1632 + UK * 32) {     // zero G
        g_G[id - 1632] = 0.f;
    }
}

// ---------------- level-2 small vectors ----------------
__global__ void __launch_bounds__(256) smallvec_kernel()
{
    int id = blockIdx.x * 256 + threadIdx.x;
    if (id < 320) {                       // win_i = sum_j Mq[j][i] ckin[j]
        float acc = 0.f;
        for (int j = 0; j < E_; j++) acc += g_Mq[j * E_ + id] * g_ckin[j];
        g_wv[id] = acc;
    } else if (id < 640) {                // wout
        int i = id - 320;
        float acc = 0.f;
        for (int j = 0; j < E_; j++) acc += g_Mq[j * E_ + i] * g_ckout[j];
        g_wv[id] = acc;
    } else if (id < 960) {                // cqKin_c
        int c = id - 640;
        float acc = 0.f;
        for (int j = 0; j < E_; j++) acc += g_cq[j] * g_MKin[j * E_ + c];
        g_cqK[c] = acc;
    } else if (id < 1280) {               // cqKout
        int c = id - 960;
        float acc = 0.f;
        for (int j = 0; j < E_; j++) acc += g_cq[j] * g_MKout[j * E_ + c];
        g_cqK[320 + c] = acc;
    } else if (id < 1310) {               // G row 640 = PW^T cvin
        int o = id - 1280;
        float acc = 0.f;
        for (int c = 0; c < E_; c++) acc += g_cvin[c] * g_PW[c * 32 + o];
        g_G[640 * 32 + o] = acc;
    } else if (id < 1340) {               // G row 641 = PW^T cvout
        int o = id - 1310;
        float acc = 0.f;
        for (int c = 0; c < E_; c++) acc += g_cvout[c] * g_PW[c * 32 + o];
        g_G[641 * 32 + o] = acc;
    } else if (id == 1340) {              // bin
        float acc = 0.f;
        for (int j = 0; j < E_; j++) acc += g_cq[j] * g_ckin[j];
        g_wb[0] = acc;
    } else if (id == 1341) {              // bout
        float acc = 0.f;
        for (int j = 0; j < E_; j++) acc += g_cq[j] * g_ckout[j];
        g_wb[1] = acc;
    }
}

// ---------------- per-node 5-head attention ----------------
__global__ void __launch_bounds__(256) attn_kernel(
    const int* __restrict__ in_idx, const int* __restrict__ out_idx,
    const float* __restrict__ in_b, const float* __restrict__ out_b)
{
    int n = blockIdx.x;
    int tid = threadIdx.x;
    extern __shared__ float sm[];
    float* Qs = sm;                 // 16*SR
    float* Ks = Qs + T_ * SR;
    float* Vs = Ks + T_ * SR;
    float* A0 = Vs + T_ * SR;       // 1280
    float* A1 = A0 + 1280;          // 1280
    __shared__ int rows[T_];

    for (int side = 0; side < 2; side++) {
        const int* idx = side ? out_idx : in_idx;
        const float* bias = side ? out_b : in_b;
        if (tid < T_) rows[tid] = tid ? idx[n * D_ + tid - 1] : n;
        __syncthreads();
        int colbase = side * 960;
        // gather Q,K,V rows + bias (float4)
        for (int e = tid; e < 3840; e += 256) {
            int a = e / 1280, r = e - a * 1280;
            int t = r / 80, j = (r - t * 80) * 4;
            const float* src = g_XP + (size_t)rows[t] * 1920 + colbase + a * 320 + j;
            float4 v = *(const float4*)src;
            float4 bv = *(const float4*)(bias + a * 320 + j);
            v.x += bv.x; v.y += bv.y; v.z += bv.z; v.w += bv.w;
            float* dst = (a == 0 ? Qs : (a == 1 ? Ks : Vs)) + t * SR + j;
            *(float4*)dst = v;
        }
        __syncthreads();
        // scores: 80 tiles of 4x4 (l,m) x 2 d-halves -> 160 threads
        if (tid < 160) {
            int dh = tid & 1;
            int tile = tid >> 1;
            int h = tile >> 4, rem = tile & 15;
            int l0 = (rem >> 2) * 4, mm0 = (rem & 3) * 4;
            const float* qb = Qs + h * 64 + dh * 32;
            const float* kb = Ks + h * 64 + dh * 32;
            float acc[4][4] = {};
            #pragma unroll
            for (int d = 0; d < 32; d += 4) {
                float4 q[4], k4[4];
                #pragma unroll
                for (int r = 0; r < 4; r++) q[r] = *(const float4*)(qb + (l0 + r) * SR + d);
                #pragma unroll
                for (int c = 0; c < 4; c++) k4[c] = *(const float4*)(kb + (mm0 + c) * SR + d);
                #pragma unroll
                for (int r = 0; r < 4; r++)
                    #pragma unroll
                    for (int c = 0; c < 4; c++)
                        acc[r][c] += q[r].x * k4[c].x + q[r].y * k4[c].y
                                   + q[r].z * k4[c].z + q[r].w * k4[c].w;
            }
            float* dst = dh ? A1 : A0;
            #pragma unroll
            for (int r = 0; r < 4; r++)
                #pragma unroll
                for (int c = 0; c < 4; c++)
                    dst[(h * 16 + l0 + r) * 16 + mm0 + c] = acc[r][c];
        }
        __syncthreads();
        // softmax: 80 (h,l) rows of 16
        if (tid < 80) {
            int base = tid * 16;
            float v[16];
            float mx = -1e30f;
            #pragma unroll
            for (int m = 0; m < 16; m++) {
                v[m] = (A0[base + m] + A1[base + m]) * 0.125f;
                mx = fmaxf(mx, v[m]);
            }
            float ssum = 0.f;
            #pragma unroll
            for (int m = 0; m < 16; m++) { v[m] = __expf(v[m] - mx); ssum += v[m]; }
            float inv = 1.f / ssum;
            #pragma unroll
            for (int m = 0; m < 16; m++) A0[base + m] = v[m] * inv;
        }
        __syncthreads();
        // ctx = A @ V : 2t x 4j tiles
        float* ctxout = g_CTX + (size_t)n * 10240 + side * 5120;
        for (int u = tid; u < 640; u += 256) {
            int tp = u / 80;
            int j = (u - tp * 80) * 4;
            int h = j >> 6;
            int t0 = tp * 2;
            float ar0[16], ar1[16];
            #pragma unroll
            for (int q = 0; q < 4; q++) {
                *(float4*)&ar0[q * 4] = *(const float4*)&A0[(h * 16 + t0) * 16 + q * 4];
                *(float4*)&ar1[q * 4] = *(const float4*)&A0[(h * 16 + t0 + 1) * 16 + q * 4];
            }
            float4 acc0 = make_float4(0.f, 0.f, 0.f, 0.f);
            float4 acc1 = make_float4(0.f, 0.f, 0.f, 0.f);
            #pragma unroll
            for (int m = 0; m < 16; m++) {
                float4 v4 = *(const float4*)(Vs + m * SR + j);
                acc0.x += ar0[m] * v4.x; acc0.y += ar0[m] * v4.y;
                acc0.z += ar0[m] * v4.z; acc0.w += ar0[m] * v4.w;
                acc1.x += ar1[m] * v4.x; acc1.y += ar1[m] * v4.y;
                acc1.z += ar1[m] * v4.z; acc1.w += ar1[m] * v4.w;
            }
            *(float4*)(ctxout + (size_t)t0 * 320 + j) = acc0;
            *(float4*)(ctxout + (size_t)(t0 + 1) * 320 + j) = acc1;
        }
        __syncthreads();
    }
}

// ---------------- final-layer scores + softmax + U ----------------
__global__ void __launch_bounds__(256) finscore_kernel()
{
    int n = blockIdx.x;
    int tid = threadIdx.x, lane = tid & 31, w = tid >> 5;
    __shared__ float Ts[640];
    __shared__ float sA[32];
    __shared__ float sc[2];
    __shared__ float s_sain;
    const float* ctxn = g_CTX + (size_t)n * 10240;

    for (int i = tid; i < 640; i += 256) Ts[i] = g_TT[(size_t)n * 640 + i];
    __syncthreads();
    // 32 token score dots
    #pragma unroll
    for (int ii = 0; ii < 4; ii++) {
        int t = w * 4 + ii;
        int side = t >> 4, tok = t & 15;
        const float* cr = ctxn + side * 5120 + tok * 320;
        const float* tv = Ts + side * 320;
        float acc = 0.f;
        #pragma unroll
        for (int i = 0; i < 10; i++) acc += cr[lane + 32 * i] * tv[lane + 32 * i];
        #pragma unroll
        for (int o = 16; o; o >>= 1) acc += __shfl_xor_sync(0xffffffffu, acc, o);
        if (lane == 0) sA[t] = acc;
    }
    if (w < 2) {     // sc = ctx0 . w_side + b_side
        const float* cr = ctxn;
        const float* tv = g_wv + w * 320;
        float acc = 0.f;
        #pragma unroll
        for (int i = 0; i < 10; i++) acc += cr[lane + 32 * i] * tv[lane + 32 * i];
        #pragma unroll
        for (int o = 16; o; o >>= 1) acc += __shfl_xor_sync(0xffffffffu, acc, o);
        if (lane == 0) sc[w] = acc + g_wb[w];
    }
    __syncthreads();
    if (tid < 32) {  // softmax over 32 (scale = 320^-0.5)
        float v = (sA[tid] + sc[tid >> 4]) * 0.05590169943749474f;
        float mx = v;
        #pragma unroll
        for (int o = 16; o; o >>= 1) mx = fmaxf(mx, __shfl_xor_sync(0xffffffffu, mx, o));
        float e = __expf(v - mx);
        float ssum = e;
        #pragma unroll
        for (int o = 16; o; o >>= 1) ssum += __shfl_xor_sync(0xffffffffu, ssum, o);
        float a = e / ssum;
        sA[tid] = a;
        float ain = (tid < 16) ? a : 0.f;
        #pragma unroll
        for (int o = 16; o; o >>= 1) ain += __shfl_xor_sync(0xffffffffu, ain, o);
        if (tid == 0) s_sain = ain;
    }
    __syncthreads();
    float sain = s_sain;
    float* urow = g_U + (size_t)n * UK;
    for (int i = tid; i < UK; i += 256) {
        float val;
        if (i < 320) {
            float acc = 0.f;
            #pragma unroll
            for (int t = 0; t < 16; t++) acc += sA[t] * ctxn[t * 320 + i];
            val = acc;
        } else if (i < 640) {
            int ii2 = i - 320;
            float acc = 0.f;
            #pragma unroll
            for (int t = 0; t < 16; t++) acc += sA[16 + t] * ctxn[5120 + t * 320 + ii2];
            val = acc;
        } else if (i == 640) val = sain;
        else if (i == 641) val = 1.f - sain;
        else val = 0.f;
        urow[i] = val;
    }
}

// ---------------- out = elu(U @ G + cW) ----------------
__global__ void __launch_bounds__(256) outproj_kernel(float* __restrict__ out)
{
    extern __shared__ float sm2[];
    float* Gs = sm2;                 // 656*32
    float* Us = sm2 + UK * 32;       // 32*656
    int tid = threadIdx.x;
    int n0 = blockIdx.x * 32;

    for (int i = tid; i < (UK * 32) / 4; i += 256)
        ((float4*)Gs)[i] = ((const float4*)g_G)[i];
    const float* usrc = g_U + (size_t)n0 * UK;
    for (int i = tid; i < (32 * UK) / 4; i += 256)
        ((float4*)Us)[i] = ((const float4*)usrc)[i];
    __syncthreads();

    int w = tid >> 5, lane = tid & 31;
    for (int nn = w; nn < 32; nn += 8) {
        int n = n0 + nn;
        const float* ur = Us + nn * UK;
        float acc = 0.f;
        for (int i = 0; i < 642; i += 2) {
            acc += ur[i] * Gs[i * 32 + lane];
            acc += ur[i + 1] * Gs[(i + 1) * 32 + lane];
        }
        if (lane < OUT_ && n < N_NODES) {
            acc += g_cW[lane];
            out[n * OUT_ + lane] = acc > 0.f ? acc : expm1f(acc);
        }
    }
}

// ---------------- host ----------------
extern "C" void kernel_launch(void* const* d_in, const int* in_sizes, int n_in,
                              void* d_out, int out_size)
{
    const float* X         = (const float*)d_in[0];
    const int*   in_idx    = (const int*)  d_in[1];
    const int*   out_idx   = (const int*)  d_in[2];
    const float* in_Wq     = (const float*)d_in[3];
    const float* in_Wk     = (const float*)d_in[4];
    const float* in_Wv     = (const float*)d_in[5];
    const float* in_qkv_w  = (const float*)d_in[6];
    const float* in_qkv_b  = (const float*)d_in[7];
    const float* in_o_w    = (const float*)d_in[8];
    const float* in_o_b    = (const float*)d_in[9];
    const float* out_Wq    = (const float*)d_in[10];
    const float* out_Wk    = (const float*)d_in[11];
    const float* out_Wv    = (const float*)d_in[12];
    const float* out_qkv_w = (const float*)d_in[13];
    const float* out_qkv_b = (const float*)d_in[14];
    const float* out_o_w   = (const float*)d_in[15];
    const float* out_o_b   = (const float*)d_in[16];
    const float* fin_qkv_w = (const float*)d_in[17];
    const float* fin_qkv_b = (const float*)d_in[18];
    const float* fin_o_w   = (const float*)d_in[19];
    const float* fin_o_b   = (const float*)d_in[20];
    const float* Wmat      = (const float*)d_in[21];
    float* out = (float*)d_out;

    float *pMA, *pMq, *pMKin, *pMKout, *pMVin, *pMVout, *pPW, *pMqKcat, *pG,
          *pXP, *pCTX, *pTT, *pU, *pcqK;
    cudaGetSymbolAddress((void**)&pMA, g_MA);
    cudaGetSymbolAddress((void**)&pMq, g_Mq);
    cudaGetSymbolAddress((void**)&pMKin, g_MKin);
    cudaGetSymbolAddress((void**)&pMKout, g_MKout);
    cudaGetSymbolAddress((void**)&pMVin, g_MVin);
    cudaGetSymbolAddress((void**)&pMVout, g_MVout);
    cudaGetSymbolAddress((void**)&pPW, g_PW);
    cudaGetSymbolAddress((void**)&pMqKcat, g_MqKcat);
    cudaGetSymbolAddress((void**)&pG, g_G);
    cudaGetSymbolAddress((void**)&pXP, g_XP);
    cudaGetSymbolAddress((void**)&pCTX, g_CTX);
    cudaGetSymbolAddress((void**)&pTT, g_TT);
    cudaGetSymbolAddress((void**)&pU, g_U);
    cudaGetSymbolAddress((void**)&pcqK, g_cqK);

    const int ATTN_SMEM = (3 * T_ * SR + 2 * 1280) * (int)sizeof(float);
    const int OUT_SMEM  = (2 * UK * 32) * (int)sizeof(float);
    cudaFuncSetAttribute(attn_kernel, cudaFuncAttributeMaxDynamicSharedMemorySize, ATTN_SMEM);
    cudaFuncSetAttribute(outproj_kernel, cudaFuncAttributeMaxDynamicSharedMemorySize, OUT_SMEM);

    // ---- compose level 1 (batched, z=12) ----
    GemmBatch L1 = {};
    const float* Ws6[6] = {in_Wq, in_Wk, in_Wv, out_Wq, out_Wk, out_Wv};
    const float* Qw6[6] = {in_qkv_w, in_qkv_w + E_ * E_, in_qkv_w + 2 * E_ * E_,
                           out_qkv_w, out_qkv_w + E_ * E_, out_qkv_w + 2 * E_ * E_};
    for (int s = 0; s < 6; s++)
        L1.d[s] = {Qw6[s], Ws6[s], pMA + s * E_ * E_, nullptr,
                   E_, E_, E_, E_, E_, E_, 0};
    L1.d[6]  = {fin_qkv_w,               in_o_w,  pMq,    nullptr, E_, E_,  E_, E_, E_, E_, 1};
    L1.d[7]  = {fin_qkv_w + E_ * E_,     in_o_w,  pMKin,  nullptr, E_, E_,  E_, E_, E_, E_, 1};
    L1.d[8]  = {fin_qkv_w + E_ * E_,     out_o_w, pMKout, nullptr, E_, E_,  E_, E_, E_, E_, 1};
    L1.d[9]  = {fin_qkv_w + 2 * E_ * E_, in_o_w,  pMVin,  nullptr, E_, E_,  E_, E_, E_, E_, 1};
    L1.d[10] = {fin_qkv_w + 2 * E_ * E_, out_o_w, pMVout, nullptr, E_, E_,  E_, E_, E_, E_, 1};
    L1.d[11] = {fin_o_w,                 Wmat,    pPW,    nullptr, E_, OUT_, E_, E_, OUT_, 32, 2};
    sgemm64<<<dim3(5, 5, 12), 256>>>(L1);

    // ---- raw-input small vectors + zero G ----
    compose_small2<<<(1632 + UK * 32 + 255) / 256, 256>>>(
        fin_qkv_w, fin_qkv_b, fin_o_b, in_o_b, out_o_b, Wmat);

    // ---- compose level 2 (batched, z=4) ----
    GemmBatch L2 = {};
    L2.d[0] = {pMq,    pMKin,  pMqKcat,       nullptr, E_, E_,  E_, E_, E_, 640, 2};
    L2.d[1] = {pMq,    pMKout, pMqKcat + E_,  nullptr, E_, E_,  E_, E_, E_, 640, 2};
    L2.d[2] = {pMVin,  pPW,    pG,            nullptr, E_, OUT_, E_, E_, 32, 32, 2};
    L2.d[3] = {pMVout, pPW,    pG + E_ * 32,  nullptr, E_, OUT_, E_, E_, 32, 32, 2};
    sgemm64<<<dim3(5, 5, 4), 256>>>(L2);

    // ---- level-2 vectors ----
    smallvec_kernel<<<6, 256>>>();

    // ---- XP = X @ MA^T ----
    GemmDesc xp = {X, pMA, pXP, nullptr, N_NODES, 1920, E_, E_, E_, 1920, 0};
    sgemm128<<<dim3(15, 79), 256>>>(xp);

    // ---- per-node attention ----
    attn_kernel<<<N_NODES, 256, ATTN_SMEM>>>(in_idx, out_idx, in_qkv_b, out_qkv_b);

    // ---- [Tin|Tout] = ctx0 @ MqKcat + cqK ----
    GemmDesc tt = {pCTX, pMqKcat, pTT, pcqK, N_NODES, 640, E_, 10240, 640, 640, 1};
    sgemm128<<<dim3(5, 79), 256>>>(tt);

    // ---- final scores + softmax + U ----
    finscore_kernel<<<N_NODES, 256>>>();

    // ---- out = elu(U @ G + cW) ----
    outproj_kernel<<<(N_NODES + 31) / 32, 256, OUT_SMEM>>>(out);
}

// round 6
// speedup vs baseline: 1.7960x; 1.1371x over previous
#include <cuda_runtime.h>
#include <cstdint>
#include <cstddef>

#define N_NODES 10000
#define E_ 320
#define D_ 15
#define T_ 16
#define OUT_ 30
#define UK 656
#define SR 324

// ---------------- scratch (device globals) ----------------
__device__ float g_MA[6 * E_ * E_];        // composed QKV mats [1920][320]
__device__ float g_Mq[E_ * E_];
__device__ float g_MKin[E_ * E_];
__device__ float g_MKout[E_ * E_];
__device__ float g_MVin[E_ * E_];
__device__ float g_MVout[E_ * E_];
__device__ float g_PW[E_ * 32];            // fo_w^T @ W, padded to 32 cols
__device__ float g_MqKcat[E_ * 640];       // [320][640] = [Mq^T MKin | Mq^T MKout]
__device__ float g_G[UK * 32];             // [656][32] out-projection matrix
__device__ float g_cq[E_];
__device__ float g_ckin[E_];
__device__ float g_ckout[E_];
__device__ float g_cvin[E_];
__device__ float g_cvout[E_];
__device__ float g_cW[32];
__device__ float g_wv[640];                // [win | wout]
__device__ float g_wb[2];                  // bin, bout
__device__ float g_cqK[640];               // [cq@MKin | cq@MKout]
__device__ float g_XP[(size_t)N_NODES * 1920];
__device__ float g_CTX[(size_t)N_NODES * 10240];
__device__ float g_TT[(size_t)N_NODES * 640];
__device__ float g_U[(size_t)(N_NODES + 32) * UK];

struct GemmDesc {
    const float* A; const float* B; float* C; const float* bias;
    int M, N, K, lda, ldb, ldc, op;  // op: 0=NT, 1=NN, 2=TN
};
struct GemmBatch { GemmDesc d[12]; };

// ---------------- big GEMM: 128x128 tile, 8x8 micro, double-buffered ----------------
// OP==0 (NT): B [N][K];  OP==1 (NN): B [K][N].  Requires N%128==0, K%16==0,
// all pointers/lds float4-aligned. M may have a tail (guarded).
template <int OP>
__global__ void __launch_bounds__(256) sgemm128(GemmDesc g)
{
    __shared__ float As[2][16][132];
    __shared__ float Bs[2][16][132];
    int tid = threadIdx.x;
    int tx = tid & 15, ty = tid >> 4;
    int m0 = blockIdx.y * 128, n0 = blockIdx.x * 128;
    float acc[8][8] = {};

    // A load coords: 2 x float4 per thread
    int a_m = tid >> 2, a_k = (tid & 3) << 2;
    bool a0ok = (m0 + a_m) < g.M;
    bool a1ok = (m0 + a_m + 64) < g.M;
    const float* Ar0 = g.A + (size_t)(m0 + a_m) * g.lda + a_k;
    const float* Ar1 = g.A + (size_t)(m0 + a_m + 64) * g.lda + a_k;
    // B load coords
    int b_n = tid >> 2, b_k4 = (tid & 3) << 2;   // OP==0
    int b_k = tid >> 5, b_nq = (tid & 31) << 2;  // OP==1
    const float* Br0;
    const float* Br1;
    if (OP == 0) {
        Br0 = g.B + (size_t)(n0 + b_n) * g.ldb + b_k4;
        Br1 = g.B + (size_t)(n0 + b_n + 64) * g.ldb + b_k4;
    } else {
        Br0 = g.B + (size_t)b_k * g.ldb + n0 + b_nq;
        Br1 = g.B + (size_t)(b_k + 8) * g.ldb + n0 + b_nq;
    }

    const float4 fz = make_float4(0.f, 0.f, 0.f, 0.f);
    float4 pa0 = a0ok ? *(const float4*)Ar0 : fz;
    float4 pa1 = a1ok ? *(const float4*)Ar1 : fz;
    float4 pb0 = *(const float4*)Br0;
    float4 pb1 = *(const float4*)Br1;

    // store prologue tile -> buffer 0
    As[0][a_k + 0][a_m] = pa0.x; As[0][a_k + 1][a_m] = pa0.y;
    As[0][a_k + 2][a_m] = pa0.z; As[0][a_k + 3][a_m] = pa0.w;
    As[0][a_k + 0][a_m + 64] = pa1.x; As[0][a_k + 1][a_m + 64] = pa1.y;
    As[0][a_k + 2][a_m + 64] = pa1.z; As[0][a_k + 3][a_m + 64] = pa1.w;
    if (OP == 0) {
        Bs[0][b_k4 + 0][b_n] = pb0.x; Bs[0][b_k4 + 1][b_n] = pb0.y;
        Bs[0][b_k4 + 2][b_n] = pb0.z; Bs[0][b_k4 + 3][b_n] = pb0.w;
        Bs[0][b_k4 + 0][b_n + 64] = pb1.x; Bs[0][b_k4 + 1][b_n + 64] = pb1.y;
        Bs[0][b_k4 + 2][b_n + 64] = pb1.z; Bs[0][b_k4 + 3][b_n + 64] = pb1.w;
    } else {
        *(float4*)&Bs[0][b_k][b_nq] = pb0;
        *(float4*)&Bs[0][b_k + 8][b_nq] = pb1;
    }
    __syncthreads();

    int buf = 0;
    for (int k0 = 0; k0 < g.K; k0 += 16) {
        bool nxt = (k0 + 16) < g.K;
        if (nxt) {
            int ko = k0 + 16;
            pa0 = a0ok ? *(const float4*)(Ar0 + ko) : fz;
            pa1 = a1ok ? *(const float4*)(Ar1 + ko) : fz;
            if (OP == 0) {
                pb0 = *(const float4*)(Br0 + ko);
                pb1 = *(const float4*)(Br1 + ko);
            } else {
                pb0 = *(const float4*)(Br0 + (size_t)ko * g.ldb);
                pb1 = *(const float4*)(Br1 + (size_t)ko * g.ldb);
            }
        }
        #pragma unroll
        for (int kk = 0; kk < 16; kk++) {
            float a[8], b[8];
            *(float4*)&a[0] = *(float4*)&As[buf][kk][ty * 8];
            *(float4*)&a[4] = *(float4*)&As[buf][kk][ty * 8 + 4];
            *(float4*)&b[0] = *(float4*)&Bs[buf][kk][tx * 8];
            *(float4*)&b[4] = *(float4*)&Bs[buf][kk][tx * 8 + 4];
            #pragma unroll
            for (int r = 0; r < 8; r++)
                #pragma unroll
                for (int c = 0; c < 8; c++)
                    acc[r][c] += a[r] * b[c];
        }
        if (nxt) {
            int nb = buf ^ 1;
            As[nb][a_k + 0][a_m] = pa0.x; As[nb][a_k + 1][a_m] = pa0.y;
            As[nb][a_k + 2][a_m] = pa0.z; As[nb][a_k + 3][a_m] = pa0.w;
            As[nb][a_k + 0][a_m + 64] = pa1.x; As[nb][a_k + 1][a_m + 64] = pa1.y;
            As[nb][a_k + 2][a_m + 64] = pa1.z; As[nb][a_k + 3][a_m + 64] = pa1.w;
            if (OP == 0) {
                Bs[nb][b_k4 + 0][b_n] = pb0.x; Bs[nb][b_k4 + 1][b_n] = pb0.y;
                Bs[nb][b_k4 + 2][b_n] = pb0.z; Bs[nb][b_k4 + 3][b_n] = pb0.w;
                Bs[nb][b_k4 + 0][b_n + 64] = pb1.x; Bs[nb][b_k4 + 1][b_n + 64] = pb1.y;
                Bs[nb][b_k4 + 2][b_n + 64] = pb1.z; Bs[nb][b_k4 + 3][b_n + 64] = pb1.w;
            } else {
                *(float4*)&Bs[nb][b_k][b_nq] = pb0;
                *(float4*)&Bs[nb][b_k + 8][b_nq] = pb1;
            }
            __syncthreads();
            buf = nb;
        }
    }
    #pragma unroll
    for (int r = 0; r < 8; r++) {
        int gm = m0 + ty * 8 + r;
        if (gm >= g.M) break;
        #pragma unroll
        for (int c = 0; c < 8; c++) {
            int gn = n0 + tx * 8 + c;
            g.C[(size_t)gm * g.ldc + gn] = acc[r][c] + (g.bias ? g.bias[gn] : 0.f);
        }
    }
}

// ---------------- small batched GEMM: 64x64 tile, 4x4 micro ----------------
__global__ void __launch_bounds__(256) sgemm64(GemmBatch batch)
{
    GemmDesc g = batch.d[blockIdx.z];
    int m0 = blockIdx.y * 64, n0 = blockIdx.x * 64;
    if (m0 >= g.M || n0 >= g.N) return;
    __shared__ float As[64][17];
    __shared__ float Bs[64][17];
    int tid = threadIdx.x;
    int tx = tid & 15, ty = tid >> 4;
    float acc[4][4] = {};

    for (int k0 = 0; k0 < g.K; k0 += 16) {
        if (g.op == 2) {   // A [K][M]
            #pragma unroll
            for (int i = 0; i < 4; i++) {
                int li = tid + 256 * i;
                int m = li & 63, k = li >> 6;
                int gm = m0 + m;
                As[m][k] = (gm < g.M) ? g.A[(size_t)(k0 + k) * g.lda + gm] : 0.f;
            }
        } else {           // A [M][K]
            #pragma unroll
            for (int i = 0; i < 4; i++) {
                int li = tid + 256 * i;
                int k = li & 15, m = li >> 4;
                int gm = m0 + m;
                As[m][k] = (gm < g.M) ? g.A[(size_t)gm * g.lda + k0 + k] : 0.f;
            }
        }
        if (g.op == 0) {   // B [N][K]
            #pragma unroll
            for (int i = 0; i < 4; i++) {
                int li = tid + 256 * i;
                int k = li & 15, n = li >> 4;
                int gn = n0 + n;
                Bs[n][k] = (gn < g.N) ? g.B[(size_t)gn * g.ldb + k0 + k] : 0.f;
            }
        } else {           // B [K][N]
            #pragma unroll
            for (int i = 0; i < 4; i++) {
                int li = tid + 256 * i;
                int n = li & 63, k = li >> 6;
                int gn = n0 + n;
                Bs[n][k] = (gn < g.N) ? g.B[(size_t)(k0 + k) * g.ldb + gn] : 0.f;
            }
        }
        __syncthreads();
        #pragma unroll
        for (int kk = 0; kk < 16; kk++) {
            float af[4], bf[4];
            #pragma unroll
            for (int r = 0; r < 4; r++) af[r] = As[ty * 4 + r][kk];
            #pragma unroll
            for (int c = 0; c < 4; c++) bf[c] = Bs[tx * 4 + c][kk];
            #pragma unroll
            for (int r = 0; r < 4; r++)
                #pragma unroll
                for (int c = 0; c < 4; c++)
                    acc[r][c] += af[r] * bf[c];
        }
        __syncthreads();
    }
    #pragma unroll
    for (int r = 0; r < 4; r++) {
        int gm = m0 + ty * 4 + r;
        if (gm >= g.M) continue;
        #pragma unroll
        for (int c = 0; c < 4; c++) {
            int gn = n0 + tx * 4 + c;
            if (gn < g.N)
                g.C[(size_t)gm * g.ldc + gn] = acc[r][c] + (g.bias ? g.bias[gn] : 0.f);
        }
    }
}

// ---------------- warp-parallel raw-input vectors + zero init of G ----------------
// blocks [0,204): 8 warps each, one output per warp (1632 outputs)
// blocks [204,225): zero g_G (5248 float4)
__global__ void __launch_bounds__(256) compose_small2(
    const float* __restrict__ finw, const float* __restrict__ finb,
    const float* __restrict__ fob,
    const float* __restrict__ inob, const float* __restrict__ outob,
    const float* __restrict__ W)
{
    if (blockIdx.x >= 204) {
        int i = (blockIdx.x - 204) * 256 + threadIdx.x;
        if (i < (UK * 32) / 4) ((float4*)g_G)[i] = make_float4(0.f, 0.f, 0.f, 0.f);
        return;
    }
    int gw = blockIdx.x * 8 + (threadIdx.x >> 5);
    int lane = threadIdx.x & 31;
    float acc = 0.f;
    if (gw < 1600) {
        int grp = gw / 320, j = gw - grp * 320;
        const float* row;
        const float* vec;
        float b;
        if (grp == 0)      { row = finw + (size_t)j * E_;            vec = inob;  b = finb[j]; }
        else if (grp == 1) { row = finw + (size_t)(E_ + j) * E_;     vec = inob;  b = finb[E_ + j]; }
        else if (grp == 2) { row = finw + (size_t)(E_ + j) * E_;     vec = outob; b = finb[E_ + j]; }
        else if (grp == 3) { row = finw + (size_t)(2 * E_ + j) * E_; vec = inob;  b = finb[2 * E_ + j]; }
        else               { row = finw + (size_t)(2 * E_ + j) * E_; vec = outob; b = finb[2 * E_ + j]; }
        #pragma unroll
        for (int i = 0; i < 10; i++) acc += row[lane + 32 * i] * vec[lane + 32 * i];
        #pragma unroll
        for (int o = 16; o; o >>= 1) acc += __shfl_xor_sync(0xffffffffu, acc, o);
        if (lane == 0) {
            acc += b;
            if (grp == 0)      g_cq[j] = acc;
            else if (grp == 1) g_ckin[j] = acc;
            else if (grp == 2) g_ckout[j] = acc;
            else if (grp == 3) g_cvin[j] = acc;
            else               g_cvout[j] = acc;
        }
    } else if (gw < 1632) {
        int o = gw - 1600;
        if (o < OUT_) {
            #pragma unroll
            for (int i = 0; i < 10; i++) {
                int k = lane + 32 * i;
                acc += fob[k] * W[k * OUT_ + o];
            }
        }
        #pragma unroll
        for (int oo = 16; oo; oo >>= 1) acc += __shfl_xor_sync(0xffffffffu, acc, oo);
        if (lane == 0) g_cW[o] = (o < OUT_) ? acc : 0.f;
    }
}

// ---------------- warp-parallel level-2 vectors (1342 warps) ----------------
__global__ void __launch_bounds__(256) smallvec_kernel()
{
    int gw = blockIdx.x * 8 + (threadIdx.x >> 5);
    int lane = threadIdx.x & 31;
    float acc = 0.f;
    if (gw < 640) {                        // wv[i] = sum_j Mq[j][i] * ck[j]
        int side = gw >= 320;
        int i = gw - side * 320;
        const float* ck = side ? g_ckout : g_ckin;
        #pragma unroll
        for (int q = 0; q < 10; q++) {
            int j = lane + 32 * q;
            acc += g_Mq[(size_t)j * E_ + i] * ck[j];
        }
        #pragma unroll
        for (int o = 16; o; o >>= 1) acc += __shfl_xor_sync(0xffffffffu, acc, o);
        if (lane == 0) g_wv[gw] = acc;
    } else if (gw < 1280) {                // cqK[c] = sum_j cq[j] * MK[j][c]
        int side = gw >= 960;
        int c = gw - 640 - side * 320;
        const float* MK = side ? g_MKout : g_MKin;
        #pragma unroll
        for (int q = 0; q < 10; q++) {
            int j = lane + 32 * q;
            acc += g_cq[j] * MK[(size_t)j * E_ + c];
        }
        #pragma unroll
        for (int o = 16; o; o >>= 1) acc += __shfl_xor_sync(0xffffffffu, acc, o);
        if (lane == 0) g_cqK[side * 320 + c] = acc;
    } else if (gw < 1340) {                // G rows 640/641 = PW^T cv
        int r = gw - 1280;
        int row = r >= 30;
        int o = r - row * 30;
        const float* cv = row ? g_cvout : g_cvin;
        #pragma unroll
        for (int q = 0; q < 10; q++) {
            int c = lane + 32 * q;
            acc += cv[c] * g_PW[c * 32 + o];
        }
        #pragma unroll
        for (int oo = 16; oo; oo >>= 1) acc += __shfl_xor_sync(0xffffffffu, acc, oo);
        if (lane == 0) g_G[(640 + row) * 32 + o] = acc;
    } else if (gw < 1342) {                // wb = cq . ck
        int w = gw - 1340;
        const float* ck = w ? g_ckout : g_ckin;
        #pragma unroll
        for (int q = 0; q < 10; q++) {
            int j = lane + 32 * q;
            acc += g_cq[j] * ck[j];
        }
        #pragma unroll
        for (int o = 16; o; o >>= 1) acc += __shfl_xor_sync(0xffffffffu, acc, o);
        if (lane == 0) g_wb[w] = acc;
    }
}

// ---------------- per-node 5-head attention ----------------
__global__ void __launch_bounds__(256) attn_kernel(
    const int* __restrict__ in_idx, const int* __restrict__ out_idx,
    const float* __restrict__ in_b, const float* __restrict__ out_b)
{
    int n = blockIdx.x;
    int tid = threadIdx.x;
    extern __shared__ float sm[];
    float* Qs = sm;                 // 16*SR
    float* Ks = Qs + T_ * SR;
    float* Vs = Ks + T_ * SR;
    float* A0 = Vs + T_ * SR;       // 1280
    float* A1 = A0 + 1280;          // 1280
    __shared__ int rows[2][T_];

    // load both sides' neighbor lists once
    if (tid < 32) {
        int s = tid >> 4, t = tid & 15;
        const int* idx = s ? out_idx : in_idx;
        rows[s][t] = t ? idx[n * D_ + t - 1] : n;
    }
    __syncthreads();

    for (int side = 0; side < 2; side++) {
        const float* bias = side ? out_b : in_b;
        int colbase = side * 960;
        // gather Q,K,V rows + bias (float4)
        for (int e = tid; e < 3840; e += 256) {
            int a = e / 1280, r = e - a * 1280;
            int t = r / 80, j = (r - t * 80) * 4;
            const float* src = g_XP + (size_t)rows[side][t] * 1920 + colbase + a * 320 + j;
            float4 v = *(const float4*)src;
            float4 bv = *(const float4*)(bias + a * 320 + j);
            v.x += bv.x; v.y += bv.y; v.z += bv.z; v.w += bv.w;
            float* dst = (a == 0 ? Qs : (a == 1 ? Ks : Vs)) + t * SR + j;
            *(float4*)dst = v;
        }
        __syncthreads();
        // scores: 80 tiles of 4x4 (l,m) x 2 d-halves -> 160 threads
        if (tid < 160) {
            int dh = tid & 1;
            int tile = tid >> 1;
            int h = tile >> 4, rem = tile & 15;
            int l0 = (rem >> 2) * 4, mm0 = (rem & 3) * 4;
            const float* qb = Qs + h * 64 + dh * 32;
            const float* kb = Ks + h * 64 + dh * 32;
            float acc[4][4] = {};
            #pragma unroll
            for (int d = 0; d < 32; d += 4) {
                float4 q[4], k4[4];
                #pragma unroll
                for (int r = 0; r < 4; r++) q[r] = *(const float4*)(qb + (l0 + r) * SR + d);
                #pragma unroll
                for (int c = 0; c < 4; c++) k4[c] = *(const float4*)(kb + (mm0 + c) * SR + d);
                #pragma unroll
                for (int r = 0; r < 4; r++)
                    #pragma unroll
                    for (int c = 0; c < 4; c++)
                        acc[r][c] += q[r].x * k4[c].x + q[r].y * k4[c].y
                                   + q[r].z * k4[c].z + q[r].w * k4[c].w;
            }
            float* dst = dh ? A1 : A0;
            #pragma unroll
            for (int r = 0; r < 4; r++)
                #pragma unroll
                for (int c = 0; c < 4; c++)
                    dst[(h * 16 + l0 + r) * 16 + mm0 + c] = acc[r][c];
        }
        __syncthreads();
        // softmax: 80 (h,l) rows of 16
        if (tid < 80) {
            int base = tid * 16;
            float v[16];
            float mx = -1e30f;
            #pragma unroll
            for (int m = 0; m < 16; m++) {
                v[m] = (A0[base + m] + A1[base + m]) * 0.125f;
                mx = fmaxf(mx, v[m]);
            }
            float ssum = 0.f;
            #pragma unroll
            for (int m = 0; m < 16; m++) { v[m] = __expf(v[m] - mx); ssum += v[m]; }
            float inv = 1.f / ssum;
            #pragma unroll
            for (int m = 0; m < 16; m++) A0[base + m] = v[m] * inv;
        }
        __syncthreads();
        // ctx = A @ V : 2t x 4j tiles
        float* ctxout = g_CTX + (size_t)n * 10240 + side * 5120;
        for (int u = tid; u < 640; u += 256) {
            int tp = u / 80;
            int j = (u - tp * 80) * 4;
            int h = j >> 6;
            int t0 = tp * 2;
            float ar0[16], ar1[16];
            #pragma unroll
            for (int q = 0; q < 4; q++) {
                *(float4*)&ar0[q * 4] = *(const float4*)&A0[(h * 16 + t0) * 16 + q * 4];
                *(float4*)&ar1[q * 4] = *(const float4*)&A0[(h * 16 + t0 + 1) * 16 + q * 4];
            }
            float4 acc0 = make_float4(0.f, 0.f, 0.f, 0.f);
            float4 acc1 = make_float4(0.f, 0.f, 0.f, 0.f);
            #pragma unroll
            for (int m = 0; m < 16; m++) {
                float4 v4 = *(const float4*)(Vs + m * SR + j);
                acc0.x += ar0[m] * v4.x; acc0.y += ar0[m] * v4.y;
                acc0.z += ar0[m] * v4.z; acc0.w += ar0[m] * v4.w;
                acc1.x += ar1[m] * v4.x; acc1.y += ar1[m] * v4.y;
                acc1.z += ar1[m] * v4.z; acc1.w += ar1[m] * v4.w;
            }
            *(float4*)(ctxout + (size_t)t0 * 320 + j) = acc0;
            *(float4*)(ctxout + (size_t)(t0 + 1) * 320 + j) = acc1;
        }
        __syncthreads();
    }
}

// ---------------- final-layer scores + softmax + U ----------------
__global__ void __launch_bounds__(256) finscore_kernel()
{
    int n = blockIdx.x;
    int tid = threadIdx.x, lane = tid & 31, w = tid >> 5;
    __shared__ float Ts[640];
    __shared__ float sA[32];
    __shared__ float sc[2];
    __shared__ float s_sain;
    const float* ctxn = g_CTX + (size_t)n * 10240;

    for (int i = tid; i < 640; i += 256) Ts[i] = g_TT[(size_t)n * 640 + i];
    __syncthreads();
    // 32 token score dots
    #pragma unroll
    for (int ii = 0; ii < 4; ii++) {
        int t = w * 4 + ii;
        int side = t >> 4, tok = t & 15;
        const float* cr = ctxn + side * 5120 + tok * 320;
        const float* tv = Ts + side * 320;
        float acc = 0.f;
        #pragma unroll
        for (int i = 0; i < 10; i++) acc += cr[lane + 32 * i] * tv[lane + 32 * i];
        #pragma unroll
        for (int o = 16; o; o >>= 1) acc += __shfl_xor_sync(0xffffffffu, acc, o);
        if (lane == 0) sA[t] = acc;
    }
    if (w < 2) {     // sc = ctx0 . w_side + b_side
        const float* cr = ctxn;
        const float* tv = g_wv + w * 320;
        float acc = 0.f;
        #pragma unroll
        for (int i = 0; i < 10; i++) acc += cr[lane + 32 * i] * tv[lane + 32 * i];
        #pragma unroll
        for (int o = 16; o; o >>= 1) acc += __shfl_xor_sync(0xffffffffu, acc, o);
        if (lane == 0) sc[w] = acc + g_wb[w];
    }
    __syncthreads();
    if (tid < 32) {  // softmax over 32 (scale = 320^-0.5)
        float v = (sA[tid] + sc[tid >> 4]) * 0.05590169943749474f;
        float mx = v;
        #pragma unroll
        for (int o = 16; o; o >>= 1) mx = fmaxf(mx, __shfl_xor_sync(0xffffffffu, mx, o));
        float e = __expf(v - mx);
        float ssum = e;
        #pragma unroll
        for (int o = 16; o; o >>= 1) ssum += __shfl_xor_sync(0xffffffffu, ssum, o);
        float a = e / ssum;
        sA[tid] = a;
        float ain = (tid < 16) ? a : 0.f;
        #pragma unroll
        for (int o = 16; o; o >>= 1) ain += __shfl_xor_sync(0xffffffffu, ain, o);
        if (tid == 0) s_sain = ain;
    }
    __syncthreads();
    float* urow = g_U + (size_t)n * UK;
    if (tid < 160) {          // 160 float4 columns = 640 floats
        int side = tid >= 80;
        int off = (tid - side * 80) * 4;
        const float* cb = ctxn + side * 5120;
        const float* av = sA + side * 16;
        float4 acc = make_float4(0.f, 0.f, 0.f, 0.f);
        #pragma unroll
        for (int t = 0; t < 16; t++) {
            float a = av[t];
            float4 v = *(const float4*)(cb + t * 320 + off);
            acc.x += a * v.x; acc.y += a * v.y;
            acc.z += a * v.z; acc.w += a * v.w;
        }
        *(float4*)(urow + side * 320 + off) = acc;
    } else if (tid < 164) {   // tail 640..655
        int base = 640 + (tid - 160) * 4;
        float4 v = make_float4(0.f, 0.f, 0.f, 0.f);
        if (tid == 160) { v.x = s_sain; v.y = 1.f - s_sain; }
        *(float4*)(urow + base) = v;
    }
}

// ---------------- out = elu(U @ G + cW) ----------------
__global__ void __launch_bounds__(256) outproj_kernel(float* __restrict__ out)
{
    extern __shared__ float sm2[];
    float* Gs = sm2;                 // 656*32
    float* Us = sm2 + UK * 32;       // 32*656
    int tid = threadIdx.x;
    int n0 = blockIdx.x * 32;

    for (int i = tid; i < (UK * 32) / 4; i += 256)
        ((float4*)Gs)[i] = ((const float4*)g_G)[i];
    const float* usrc = g_U + (size_t)n0 * UK;
    for (int i = tid; i < (32 * UK) / 4; i += 256)
        ((float4*)Us)[i] = ((const float4*)usrc)[i];
    __syncthreads();

    int w = tid >> 5, lane = tid & 31;
    for (int nn = w; nn < 32; nn += 8) {
        int n = n0 + nn;
        const float* ur = Us + nn * UK;
        float acc = 0.f;
        for (int i = 0; i < 642; i += 2) {
            acc += ur[i] * Gs[i * 32 + lane];
            acc += ur[i + 1] * Gs[(i + 1) * 32 + lane];
        }
        if (lane < OUT_ && n < N_NODES) {
            acc += g_cW[lane];
            out[n * OUT_ + lane] = acc > 0.f ? acc : expm1f(acc);
        }
    }
}

// ---------------- host ----------------
extern "C" void kernel_launch(void* const* d_in, const int* in_sizes, int n_in,
                              void* d_out, int out_size)
{
    const float* X         = (const float*)d_in[0];
    const int*   in_idx    = (const int*)  d_in[1];
    const int*   out_idx   = (const int*)  d_in[2];
    const float* in_Wq     = (const float*)d_in[3];
    const float* in_Wk     = (const float*)d_in[4];
    const float* in_Wv     = (const float*)d_in[5];
    const float* in_qkv_w  = (const float*)d_in[6];
    const float* in_qkv_b  = (const float*)d_in[7];
    const float* in_o_w    = (const float*)d_in[8];
    const float* in_o_b    = (const float*)d_in[9];
    const float* out_Wq    = (const float*)d_in[10];
    const float* out_Wk    = (const float*)d_in[11];
    const float* out_Wv    = (const float*)d_in[12];
    const float* out_qkv_w = (const float*)d_in[13];
    const float* out_qkv_b = (const float*)d_in[14];
    const float* out_o_w   = (const float*)d_in[15];
    const float* out_o_b   = (const float*)d_in[16];
    const float* fin_qkv_w = (const float*)d_in[17];
    const float* fin_qkv_b = (const float*)d_in[18];
    const float* fin_o_w   = (const float*)d_in[19];
    const float* fin_o_b   = (const float*)d_in[20];
    const float* Wmat      = (const float*)d_in[21];
    float* out = (float*)d_out;

    float *pMA, *pMq, *pMKin, *pMKout, *pMVin, *pMVout, *pPW, *pMqKcat, *pG,
          *pXP, *pCTX, *pTT, *pU, *pcqK;
    cudaGetSymbolAddress((void**)&pMA, g_MA);
    cudaGetSymbolAddress((void**)&pMq, g_Mq);
    cudaGetSymbolAddress((void**)&pMKin, g_MKin);
    cudaGetSymbolAddress((void**)&pMKout, g_MKout);
    cudaGetSymbolAddress((void**)&pMVin, g_MVin);
    cudaGetSymbolAddress((void**)&pMVout, g_MVout);
    cudaGetSymbolAddress((void**)&pPW, g_PW);
    cudaGetSymbolAddress((void**)&pMqKcat, g_MqKcat);
    cudaGetSymbolAddress((void**)&pG, g_G);
    cudaGetSymbolAddress((void**)&pXP, g_XP);
    cudaGetSymbolAddress((void**)&pCTX, g_CTX);
    cudaGetSymbolAddress((void**)&pTT, g_TT);
    cudaGetSymbolAddress((void**)&pU, g_U);
    cudaGetSymbolAddress((void**)&pcqK, g_cqK);

    const int ATTN_SMEM = (3 * T_ * SR + 2 * 1280) * (int)sizeof(float);
    const int OUT_SMEM  = (2 * UK * 32) * (int)sizeof(float);
    cudaFuncSetAttribute(attn_kernel, cudaFuncAttributeMaxDynamicSharedMemorySize, ATTN_SMEM);
    cudaFuncSetAttribute(outproj_kernel, cudaFuncAttributeMaxDynamicSharedMemorySize, OUT_SMEM);

    // ---- compose level 1 (batched, z=12) ----
    GemmBatch L1 = {};
    const float* Ws6[6] = {in_Wq, in_Wk, in_Wv, out_Wq, out_Wk, out_Wv};
    const float* Qw6[6] = {in_qkv_w, in_qkv_w + E_ * E_, in_qkv_w + 2 * E_ * E_,
                           out_qkv_w, out_qkv_w + E_ * E_, out_qkv_w + 2 * E_ * E_};
    for (int s = 0; s < 6; s++)
        L1.d[s] = {Qw6[s], Ws6[s], pMA + s * E_ * E_, nullptr,
                   E_, E_, E_, E_, E_, E_, 0};
    L1.d[6]  = {fin_qkv_w,               in_o_w,  pMq,    nullptr, E_, E_,  E_, E_, E_, E_, 1};
    L1.d[7]  = {fin_qkv_w + E_ * E_,     in_o_w,  pMKin,  nullptr, E_, E_,  E_, E_, E_, E_, 1};
    L1.d[8]  = {fin_qkv_w + E_ * E_,     out_o_w, pMKout, nullptr, E_, E_,  E_, E_, E_, E_, 1};
    L1.d[9]  = {fin_qkv_w + 2 * E_ * E_, in_o_w,  pMVin,  nullptr, E_, E_,  E_, E_, E_, E_, 1};
    L1.d[10] = {fin_qkv_w + 2 * E_ * E_, out_o_w, pMVout, nullptr, E_, E_,  E_, E_, E_, E_, 1};
    L1.d[11] = {fin_o_w,                 Wmat,    pPW,    nullptr, E_, OUT_, E_, E_, OUT_, 32, 2};
    sgemm64<<<dim3(5, 5, 12), 256>>>(L1);

    // ---- raw-input small vectors + zero G (warp-parallel) ----
    compose_small2<<<225, 256>>>(fin_qkv_w, fin_qkv_b, fin_o_b, in_o_b, out_o_b, Wmat);

    // ---- compose level 2 (batched, z=4) ----
    GemmBatch L2 = {};
    L2.d[0] = {pMq,    pMKin,  pMqKcat,       nullptr, E_, E_,  E_, E_, E_, 640, 2};
    L2.d[1] = {pMq,    pMKout, pMqKcat + E_,  nullptr, E_, E_,  E_, E_, E_, 640, 2};
    L2.d[2] = {pMVin,  pPW,    pG,            nullptr, E_, OUT_, E_, E_, 32, 32, 2};
    L2.d[3] = {pMVout, pPW,    pG + E_ * 32,  nullptr, E_, OUT_, E_, E_, 32, 32, 2};
    sgemm64<<<dim3(5, 5, 4), 256>>>(L2);

    // ---- level-2 vectors (warp-parallel) ----
    smallvec_kernel<<<168, 256>>>();

    // ---- XP = X @ MA^T ----
    GemmDesc xp = {X, pMA, pXP, nullptr, N_NODES, 1920, E_, E_, E_, 1920, 0};
    sgemm128<0><<<dim3(15, 79), 256>>>(xp);

    // ---- per-node attention ----
    attn_kernel<<<N_NODES, 256, ATTN_SMEM>>>(in_idx, out_idx, in_qkv_b, out_qkv_b);

    // ---- [Tin|Tout] = ctx0 @ MqKcat + cqK ----
    GemmDesc tt = {pCTX, pMqKcat, pTT, pcqK, N_NODES, 640, E_, 10240, 640, 640, 1};
    sgemm128<1><<<dim3(5, 79), 256>>>(tt);

    // ---- final scores + softmax + U ----
    finscore_kernel<<<N_NODES, 256>>>();

    // ---- out = elu(U @ G + cW) ----
    outproj_kernel<<<(N_NODES + 31) / 32, 256, OUT_SMEM>>>(out);
}